// round 3
// baseline (speedup 1.0000x reference)
#include <cuda_runtime.h>

#define NN   50000
#define FIN  336
#define HC   512
#define NH   4
#define CH   128
#define NE   500000
#define NEP  (NE + NN)

// ---------------- scratch (device globals; no allocation allowed) ----------
__device__ __align__(16) float g_h[(size_t)NN * HC];    // h = X @ W  (both layers)
__device__ __align__(16) float g_out[(size_t)NN * HC];  // aggregated output
__device__ __align__(16) float g_z[(size_t)NN * CH];    // classifier hidden
__device__ __align__(16) float g_e[(size_t)NEP * NH];   // per-edge logits -> probs
__device__ __align__(16) float g_asrc[NN * NH];
__device__ __align__(16) float g_adst[NN * NH];
__device__ __align__(16) float g_m[NN * NH];            // segment max
__device__ __align__(16) float g_s[NN * NH];            // segment sum
__device__ int g_src[NEP];
__device__ int g_dst[NEP];
__device__ int g_is64;                                  // edge_index dtype flag

// ---------------- helpers --------------------------------------------------
__device__ __forceinline__ void atomicMaxFloat(float* addr, float val) {
    if (val >= 0.0f) atomicMax((int*)addr, __float_as_int(val));
    else             atomicMin((unsigned int*)addr, __float_as_uint(val));
}

// ---------------- edge-index dtype probe + conversion ----------------------
// If the raw buffer holds int64 indices, every value read as int64 lies in
// [0, NN). If it holds int32, an int64 read combines two random int32s and is
// >= 2^32 whenever the high word is nonzero (near-certain within 64 samples).
__global__ void probe_kernel(const void* __restrict__ ei) {
    const long long* p = (const long long*)ei;
    int ok64 = 1;
    for (int i = 0; i < 64; i++) {
        long long v = p[i];
        if (v < 0 || v >= NN) ok64 = 0;
    }
    g_is64 = ok64;
}

__global__ void convert_kernel(const void* __restrict__ ei) {
    const int i = blockIdx.x * blockDim.x + threadIdx.x;
    if (i >= NEP) return;
    int s, d;
    if (i < NE) {
        if (g_is64) {
            const long long* p = (const long long*)ei;
            s = (int)p[i]; d = (int)p[NE + i];
        } else {
            const int* p = (const int*)ei;
            s = p[i]; d = p[NE + i];
        }
    } else {
        s = d = i - NE;
    }
    g_src[i] = s;
    g_dst[i] = d;
}

// ---------------- tiled SGEMM: C = act(A@B + bias) -------------------------
// A[M,K], B[K,N], C[M,N] row-major. Requires K%16==0, N%64==0.
// ACT: 0 = none, 1 = relu
template <int ACT>
__global__ void sgemm(const float* __restrict__ A, const float* __restrict__ B,
                      const float* __restrict__ bias, float* __restrict__ C,
                      int M, int N, int K) {
    __shared__ __align__(16) float As[16][64];
    __shared__ __align__(16) float Bs[16][64];
    const int tid = threadIdx.x;           // 256 threads
    const int tx = tid & 15, ty = tid >> 4;
    const int row0 = blockIdx.y * 64, col0 = blockIdx.x * 64;

    float acc[4][4] = {};

    const int ar = tid >> 2;               // 0..63   (A tile row)
    const int ac = (tid & 3) * 4;          // 0,4,8,12 (A tile col)
    const int br = tid >> 4;               // 0..15   (B tile row = k)
    const int bc = (tid & 15) * 4;         // 0..60   (B tile col)

    for (int k0 = 0; k0 < K; k0 += 16) {
        float4 av;
        const int arow = row0 + ar;
        if (arow < M) av = *(const float4*)(A + (size_t)arow * K + k0 + ac);
        else          av = make_float4(0.f, 0.f, 0.f, 0.f);
        As[ac + 0][ar] = av.x; As[ac + 1][ar] = av.y;
        As[ac + 2][ar] = av.z; As[ac + 3][ar] = av.w;

        *(float4*)&Bs[br][bc] = *(const float4*)(B + (size_t)(k0 + br) * N + col0 + bc);
        __syncthreads();

#pragma unroll
        for (int k = 0; k < 16; k++) {
            const float4 a4 = *(const float4*)&As[k][ty * 4];
            const float4 b4 = *(const float4*)&Bs[k][tx * 4];
            const float a[4] = {a4.x, a4.y, a4.z, a4.w};
            const float b[4] = {b4.x, b4.y, b4.z, b4.w};
#pragma unroll
            for (int i = 0; i < 4; i++)
#pragma unroll
                for (int j = 0; j < 4; j++)
                    acc[i][j] += a[i] * b[j];
        }
        __syncthreads();
    }

#pragma unroll
    for (int i = 0; i < 4; i++) {
        const int r = row0 + ty * 4 + i;
        if (r >= M) continue;
        const int c = col0 + tx * 4;
        float4 v = make_float4(acc[i][0], acc[i][1], acc[i][2], acc[i][3]);
        if (bias) { v.x += bias[c]; v.y += bias[c + 1]; v.z += bias[c + 2]; v.w += bias[c + 3]; }
        if (ACT == 1) {
            v.x = fmaxf(v.x, 0.f); v.y = fmaxf(v.y, 0.f);
            v.z = fmaxf(v.z, 0.f); v.w = fmaxf(v.w, 0.f);
        }
        *(float4*)(C + (size_t)r * N + c) = v;
    }
}

// ---------------- per-(node,head) attention coefficients -------------------
__global__ void alpha_kernel(const float* __restrict__ asrc,
                             const float* __restrict__ adst) {
    const int w = (blockIdx.x * blockDim.x + threadIdx.x) >> 5;
    const int lane = threadIdx.x & 31;
    if (w >= NN * NH) return;
    const int n = w >> 2, hd = w & 3;
    const float4 hv = *(const float4*)(g_h + (size_t)n * HC + hd * CH + lane * 4);
    const float4 as = *(const float4*)(asrc + hd * CH + lane * 4);
    const float4 ad = *(const float4*)(adst + hd * CH + lane * 4);
    float ss = hv.x * as.x + hv.y * as.y + hv.z * as.z + hv.w * as.w;
    float sd = hv.x * ad.x + hv.y * ad.y + hv.z * ad.z + hv.w * ad.w;
#pragma unroll
    for (int o = 16; o > 0; o >>= 1) {
        ss += __shfl_xor_sync(0xffffffffu, ss, o);
        sd += __shfl_xor_sync(0xffffffffu, sd, o);
    }
    if (lane == 0) { g_asrc[w] = ss; g_adst[w] = sd; }
}

// init m=-inf, s=0, out[n,c]=bias[c]
__global__ void init_kernel(const float* __restrict__ bias) {
    const int i = blockIdx.x * blockDim.x + threadIdx.x;
    if (i < NN * NH) { g_m[i] = __int_as_float(0xff800000); g_s[i] = 0.f; }
    if (i < NN * HC) g_out[i] = bias[i & (HC - 1)];
}

// pass 1: e = leakyrelu(a_src[src] + a_dst[dst]); segment max into m[dst]
__global__ void edge_pass1() {
    const int idx = blockIdx.x * blockDim.x + threadIdx.x;
    if (idx >= NEP * NH) return;
    const int e = idx >> 2, hd = idx & 3;
    const int s = g_src[e], d = g_dst[e];
    float v = g_asrc[s * NH + hd] + g_adst[d * NH + hd];
    v = v > 0.f ? v : 0.2f * v;
    g_e[idx] = v;
    atomicMaxFloat(&g_m[d * NH + hd], v);
}

// pass 2: p = exp(e - m[dst]); segment sum into s[dst]
__global__ void edge_pass2() {
    const int idx = blockIdx.x * blockDim.x + threadIdx.x;
    if (idx >= NEP * NH) return;
    const int e = idx >> 2, hd = idx & 3;
    const int d = g_dst[e];
    const float p = expf(g_e[idx] - g_m[d * NH + hd]);
    g_e[idx] = p;
    atomicAdd(&g_s[d * NH + hd], p);
}

// pass 3: out[dst] += (p / (s[dst]+eps)) * h[src]   (one 128-thread block/edge)
__global__ void edge_scatter() {
    const int e = blockIdx.x;
    const int t = threadIdx.x;            // 0..127 -> 4 floats each
    const int s = g_src[e], d = g_dst[e];
    const int hd = t >> 5;                // head = (t*4)/128
    const float attn = g_e[(size_t)e * NH + hd] / (g_s[d * NH + hd] + 1e-16f);
    const float4 hv = *(const float4*)(g_h + (size_t)s * HC + t * 4);
    float* o = g_out + (size_t)d * HC + t * 4;
    asm volatile("red.global.add.v4.f32 [%0], {%1,%2,%3,%4};"
                 :: "l"(o), "f"(attn * hv.x), "f"(attn * hv.y),
                    "f"(attn * hv.z), "f"(attn * hv.w)
                 : "memory");
}

__global__ void elu_kernel() {
    const int i = blockIdx.x * blockDim.x + threadIdx.x;
    if (i < NN * HC) {
        const float v = g_out[i];
        g_out[i] = v > 0.f ? v : expm1f(v);
    }
}

// final tiny GEMM: logits[n,j] = z[n,:] @ Wc2[:,j] + bc2[j]  (N_out=10)
__global__ void logits_kernel(const float* __restrict__ Wc2,
                              const float* __restrict__ bc2,
                              float* __restrict__ out) {
    const int i = blockIdx.x * blockDim.x + threadIdx.x;
    if (i >= NN * 10) return;
    const int n = i / 10, j = i - n * 10;
    const float* z = g_z + (size_t)n * CH;
    float acc = bc2[j];
#pragma unroll 4
    for (int k = 0; k < CH; k++) acc += z[k] * Wc2[k * 10 + j];
    out[i] = acc;
}

// ---------------- launch ---------------------------------------------------
extern "C" void kernel_launch(void* const* d_in, const int* in_sizes, int n_in,
                              void* d_out, int out_size) {
    const float* x   = (const float*)d_in[0];
    const void*  ei  = d_in[1];
    const float* W1  = (const float*)d_in[2];
    const float* as1 = (const float*)d_in[3];
    const float* ad1 = (const float*)d_in[4];
    const float* b1  = (const float*)d_in[5];
    const float* W2  = (const float*)d_in[6];
    const float* as2 = (const float*)d_in[7];
    const float* ad2 = (const float*)d_in[8];
    const float* b2  = (const float*)d_in[9];
    const float* Wc1 = (const float*)d_in[10];
    const float* bc1 = (const float*)d_in[11];
    const float* Wc2 = (const float*)d_in[12];
    const float* bc2 = (const float*)d_in[13];
    float* out = (float*)d_out;

    static float* p_h = nullptr; static float* p_out = nullptr; static float* p_z = nullptr;
    if (!p_h) {
        cudaGetSymbolAddress((void**)&p_h,   g_h);
        cudaGetSymbolAddress((void**)&p_out, g_out);
        cudaGetSymbolAddress((void**)&p_z,   g_z);
    }

    const int TPB = 256;
    const int alphaBlocks = (NN * NH * 32 + TPB - 1) / TPB;
    const int bigBlocks   = (NN * HC + TPB - 1) / TPB;
    const int eBlocks     = (NEP * NH + TPB - 1) / TPB;
    const int cvtBlocks   = (NEP + TPB - 1) / TPB;
    const dim3 gGemm512(HC / 64, (NN + 63) / 64);
    const dim3 gGemm128(CH / 64, (NN + 63) / 64);

    // ---- edge-index prep ----
    probe_kernel<<<1, 1>>>(ei);
    convert_kernel<<<cvtBlocks, TPB>>>(ei);

    // ---- layer 1 ----
    sgemm<0><<<gGemm512, TPB>>>(x, W1, nullptr, p_h, NN, HC, FIN);
    alpha_kernel<<<alphaBlocks, TPB>>>(as1, ad1);
    init_kernel<<<bigBlocks, TPB>>>(b1);
    edge_pass1<<<eBlocks, TPB>>>();
    edge_pass2<<<eBlocks, TPB>>>();
    edge_scatter<<<NEP, 128>>>();
    elu_kernel<<<bigBlocks, TPB>>>();

    // ---- layer 2 ----
    sgemm<0><<<gGemm512, TPB>>>(p_out, W2, nullptr, p_h, NN, HC, HC);
    alpha_kernel<<<alphaBlocks, TPB>>>(as2, ad2);
    init_kernel<<<bigBlocks, TPB>>>(b2);
    edge_pass1<<<eBlocks, TPB>>>();
    edge_pass2<<<eBlocks, TPB>>>();
    edge_scatter<<<NEP, 128>>>();

    // ---- classifier ----
    sgemm<1><<<gGemm128, TPB>>>(p_out, Wc1, bc1, p_z, NN, CH, HC);
    logits_kernel<<<(NN * 10 + TPB - 1) / TPB, TPB>>>(Wc2, bc2, out);
}

// round 5
// speedup vs baseline: 1.3231x; 1.3231x over previous
#include <cuda_runtime.h>
#include <cuda_bf16.h>
#include <cstdint>

#define NN   50000
#define FIN  336
#define HC   512
#define NH   4
#define CH   128
#define NE   500000
#define NEP  (NE + NN)
#define MPAD 50048            // 391 * 128
#define KP1  384              // FIN padded to 64-multiple
#define KP2  512

// ---------------- scratch (device globals; no allocation allowed) ----------
__device__ __align__(16) float g_h[(size_t)NN * HC];
__device__ __align__(16) float g_out[(size_t)NN * HC];
__device__ __align__(16) float g_z[(size_t)NN * CH];
__device__ __align__(16) float g_e[(size_t)NEP * NH];
__device__ __align__(16) float g_asrc[NN * NH];
__device__ __align__(16) float g_adst[NN * NH];
__device__ __align__(16) float g_m[NN * NH];
__device__ __align__(16) float g_s[NN * NH];
__device__ int g_src[NEP];
__device__ int g_dst[NEP];
__device__ int g_is64;

// bf16 split planes for tensor-core GEMM
__device__ __align__(16) __nv_bfloat16 g_ahi[(size_t)MPAD * KP2];
__device__ __align__(16) __nv_bfloat16 g_alo[(size_t)MPAD * KP2];
__device__ __align__(16) __nv_bfloat16 g_bhi[(size_t)HC * KP2];
__device__ __align__(16) __nv_bfloat16 g_blo[(size_t)HC * KP2];

// ---------------- helpers ---------------------------------------------------
__device__ __forceinline__ uint32_t smem_u32(const void* p) {
    uint32_t a;
    asm("{ .reg .u64 t; cvta.to.shared.u64 t, %1; cvt.u32.u64 %0, t; }" : "=r"(a) : "l"(p));
    return a;
}

#define LDMX4(r0, r1, r2, r3, addr)                                            \
    asm volatile("ldmatrix.sync.aligned.m8n8.x4.shared.b16 {%0,%1,%2,%3}, [%4];" \
                 : "=r"(r0), "=r"(r1), "=r"(r2), "=r"(r3) : "r"(addr))

#define MMA16816(c, a, b0, b1)                                                 \
    asm volatile("mma.sync.aligned.m16n8k16.row.col.f32.bf16.bf16.f32 "        \
                 "{%0,%1,%2,%3}, {%4,%5,%6,%7}, {%8,%9}, {%0,%1,%2,%3};"       \
                 : "+f"((c)[0]), "+f"((c)[1]), "+f"((c)[2]), "+f"((c)[3])      \
                 : "r"((a)[0]), "r"((a)[1]), "r"((a)[2]), "r"((a)[3]),         \
                   "r"(b0), "r"(b1))

// ---------------- split-bf16 conversions ------------------------------------
__global__ void conv_a(const float* __restrict__ src, int Kin, int Kpad) {
    int idx = blockIdx.x * blockDim.x + threadIdx.x;
    if (idx >= MPAD * Kpad) return;
    int row = idx / Kpad, col = idx - row * Kpad;
    float v = (row < NN && col < Kin) ? src[(size_t)row * Kin + col] : 0.f;
    __nv_bfloat16 h = __float2bfloat16(v);
    g_ahi[idx] = h;
    g_alo[idx] = __float2bfloat16(v - __bfloat162float(h));
}

// W[K,N] row-major -> Bt[N][Kpad] K-major split planes
__global__ void conv_w(const float* __restrict__ W, int K, int N, int Kpad) {
    int idx = blockIdx.x * blockDim.x + threadIdx.x;
    if (idx >= N * Kpad) return;
    int n = idx / Kpad, k = idx - n * Kpad;
    float v = (k < K) ? W[(size_t)k * N + n] : 0.f;
    __nv_bfloat16 h = __float2bfloat16(v);
    g_bhi[idx] = h;
    g_blo[idx] = __float2bfloat16(v - __bfloat162float(h));
}

// ---------------- mma.sync GEMM: C[M,N] = A[M,K] @ Bt[N,K]^T ----------------
// grid (N/64, MPAD/128), 256 threads (8 warps, 4x2). Split-bf16, 3 products.
#define APITCH 40   // halves per smem row (32 data + 8 pad), 80B
template <int ACT>
__global__ void __launch_bounds__(256, 2) gemm_mma(
    const __nv_bfloat16* __restrict__ Ahi, const __nv_bfloat16* __restrict__ Alo,
    const __nv_bfloat16* __restrict__ Bhi, const __nv_bfloat16* __restrict__ Blo,
    float* __restrict__ C, int Kpad, int ldc, const float* __restrict__ bias) {
    __shared__ __align__(16) __nv_bfloat16 sAh[128 * APITCH];
    __shared__ __align__(16) __nv_bfloat16 sAl[128 * APITCH];
    __shared__ __align__(16) __nv_bfloat16 sBh[64 * APITCH];
    __shared__ __align__(16) __nv_bfloat16 sBl[64 * APITCH];

    const int tid = threadIdx.x, lane = tid & 31, wid = tid >> 5;
    const int wm = wid & 3, wn = wid >> 2;          // warp tile: 32(M) x 32(N)
    const int n0 = blockIdx.x * 64, m0 = blockIdx.y * 128;

    const uint32_t sAh_u = smem_u32(sAh), sAl_u = smem_u32(sAl);
    const uint32_t sBh_u = smem_u32(sBh), sBl_u = smem_u32(sBl);

    // per-thread ldmatrix base offsets (bytes)
    const uint32_t aoff = ((wm * 32 + (lane & 15)) * APITCH + (lane >> 4) * 8) * 2;
    const uint32_t boff = ((wn * 32 + (lane & 7) + (lane >> 4) * 8) * APITCH
                          + ((lane >> 3) & 1) * 8) * 2;

    float acc[2][4][4] = {};

    for (int k0 = 0; k0 < Kpad; k0 += 32) {
        // ---- global -> smem (A: 512 uint4/plane, B: 256 uint4/plane) ----
        {
            const __nv_bfloat16* aH = Ahi + (size_t)m0 * Kpad + k0;
            const __nv_bfloat16* aL = Alo + (size_t)m0 * Kpad + k0;
#pragma unroll
            for (int e = tid; e < 512; e += 256) {
                const int row = e >> 2, ch = e & 3;
                const size_t gi = (size_t)row * Kpad + ch * 8;
                const int si = row * APITCH + ch * 8;
                *(uint4*)(sAh + si) = *(const uint4*)(aH + gi);
                *(uint4*)(sAl + si) = *(const uint4*)(aL + gi);
            }
            const __nv_bfloat16* bH = Bhi + (size_t)n0 * Kpad + k0;
            const __nv_bfloat16* bL = Blo + (size_t)n0 * Kpad + k0;
            {
                const int row = tid >> 2, ch = tid & 3;
                const size_t gi = (size_t)row * Kpad + ch * 8;
                const int si = row * APITCH + ch * 8;
                *(uint4*)(sBh + si) = *(const uint4*)(bH + gi);
                *(uint4*)(sBl + si) = *(const uint4*)(bL + gi);
            }
        }
        __syncthreads();

#pragma unroll
        for (int ks = 0; ks < 2; ks++) {
            const uint32_t kb = ks * 32;            // 16 halves = 32 bytes
            uint32_t ah[2][4], al[2][4], bh[2][4], bl[2][4];
#pragma unroll
            for (int mi = 0; mi < 2; mi++) {
                const uint32_t ad = aoff + mi * (16 * APITCH * 2) + kb;
                LDMX4(ah[mi][0], ah[mi][1], ah[mi][2], ah[mi][3], sAh_u + ad);
                LDMX4(al[mi][0], al[mi][1], al[mi][2], al[mi][3], sAl_u + ad);
            }
#pragma unroll
            for (int g = 0; g < 2; g++) {
                const uint32_t bd = boff + g * (16 * APITCH * 2) + kb;
                LDMX4(bh[g][0], bh[g][1], bh[g][2], bh[g][3], sBh_u + bd);
                LDMX4(bl[g][0], bl[g][1], bl[g][2], bl[g][3], sBl_u + bd);
            }
#pragma unroll
            for (int mi = 0; mi < 2; mi++)
#pragma unroll
                for (int ni = 0; ni < 4; ni++) {
                    const int g = ni >> 1, p = (ni & 1) * 2;
                    MMA16816(acc[mi][ni], ah[mi], bh[g][p], bh[g][p + 1]);
                    MMA16816(acc[mi][ni], ah[mi], bl[g][p], bl[g][p + 1]);
                    MMA16816(acc[mi][ni], al[mi], bh[g][p], bh[g][p + 1]);
                }
        }
        __syncthreads();
    }

    // ---- epilogue ----
#pragma unroll
    for (int mi = 0; mi < 2; mi++) {
        const int r0 = m0 + wm * 32 + mi * 16 + (lane >> 2);
        const int r1 = r0 + 8;
#pragma unroll
        for (int ni = 0; ni < 4; ni++) {
            const int c = n0 + wn * 32 + ni * 8 + (lane & 3) * 2;
            float2 v0 = make_float2(acc[mi][ni][0], acc[mi][ni][1]);
            float2 v1 = make_float2(acc[mi][ni][2], acc[mi][ni][3]);
            if (ACT == 1) {
                const float b0 = bias[c], b1 = bias[c + 1];
                v0.x = fmaxf(v0.x + b0, 0.f); v0.y = fmaxf(v0.y + b1, 0.f);
                v1.x = fmaxf(v1.x + b0, 0.f); v1.y = fmaxf(v1.y + b1, 0.f);
            }
            if (r0 < NN) *(float2*)(C + (size_t)r0 * ldc + c) = v0;
            if (r1 < NN) *(float2*)(C + (size_t)r1 * ldc + c) = v1;
        }
    }
}

// ---------------- edge-index dtype probe + conversion ----------------------
__global__ void probe_kernel(const void* __restrict__ ei) {
    const long long* p = (const long long*)ei;
    int ok64 = 1;
    for (int i = 0; i < 64; i++) {
        long long v = p[i];
        if (v < 0 || v >= NN) ok64 = 0;
    }
    g_is64 = ok64;
}

__global__ void convert_kernel(const void* __restrict__ ei) {
    const int i = blockIdx.x * blockDim.x + threadIdx.x;
    if (i >= NEP) return;
    int s, d;
    if (i < NE) {
        if (g_is64) {
            const long long* p = (const long long*)ei;
            s = (int)p[i]; d = (int)p[NE + i];
        } else {
            const int* p = (const int*)ei;
            s = p[i]; d = p[NE + i];
        }
    } else {
        s = d = i - NE;
    }
    g_src[i] = s;
    g_dst[i] = d;
}

// ---------------- edge/attention kernels ------------------------------------
__device__ __forceinline__ void atomicMaxFloat(float* addr, float val) {
    if (val >= 0.0f) atomicMax((int*)addr, __float_as_int(val));
    else             atomicMin((unsigned int*)addr, __float_as_uint(val));
}

__global__ void alpha_kernel(const float* __restrict__ asrc,
                             const float* __restrict__ adst) {
    const int w = (blockIdx.x * blockDim.x + threadIdx.x) >> 5;
    const int lane = threadIdx.x & 31;
    if (w >= NN * NH) return;
    const int n = w >> 2, hd = w & 3;
    const float4 hv = *(const float4*)(g_h + (size_t)n * HC + hd * CH + lane * 4);
    const float4 as = *(const float4*)(asrc + hd * CH + lane * 4);
    const float4 ad = *(const float4*)(adst + hd * CH + lane * 4);
    float ss = hv.x * as.x + hv.y * as.y + hv.z * as.z + hv.w * as.w;
    float sd = hv.x * ad.x + hv.y * ad.y + hv.z * ad.z + hv.w * ad.w;
#pragma unroll
    for (int o = 16; o > 0; o >>= 1) {
        ss += __shfl_xor_sync(0xffffffffu, ss, o);
        sd += __shfl_xor_sync(0xffffffffu, sd, o);
    }
    if (lane == 0) { g_asrc[w] = ss; g_adst[w] = sd; }
}

__global__ void init_kernel(const float* __restrict__ bias) {
    const int i = blockIdx.x * blockDim.x + threadIdx.x;
    if (i < NN * NH) { g_m[i] = __int_as_float(0xff800000); g_s[i] = 0.f; }
    if (i < NN * HC) g_out[i] = bias[i & (HC - 1)];
}

__global__ void edge_pass1() {
    const int idx = blockIdx.x * blockDim.x + threadIdx.x;
    if (idx >= NEP * NH) return;
    const int e = idx >> 2, hd = idx & 3;
    const int s = g_src[e], d = g_dst[e];
    float v = g_asrc[s * NH + hd] + g_adst[d * NH + hd];
    v = v > 0.f ? v : 0.2f * v;
    g_e[idx] = v;
    atomicMaxFloat(&g_m[d * NH + hd], v);
}

__global__ void edge_pass2() {
    const int idx = blockIdx.x * blockDim.x + threadIdx.x;
    if (idx >= NEP * NH) return;
    const int e = idx >> 2, hd = idx & 3;
    const int d = g_dst[e];
    const float p = expf(g_e[idx] - g_m[d * NH + hd]);
    g_e[idx] = p;
    atomicAdd(&g_s[d * NH + hd], p);
}

__global__ void edge_scatter() {
    const int e = blockIdx.x;
    const int t = threadIdx.x;
    const int s = g_src[e], d = g_dst[e];
    const int hd = t >> 5;
    const float attn = g_e[(size_t)e * NH + hd] / (g_s[d * NH + hd] + 1e-16f);
    const float4 hv = *(const float4*)(g_h + (size_t)s * HC + t * 4);
    float* o = g_out + (size_t)d * HC + t * 4;
    asm volatile("red.global.add.v4.f32 [%0], {%1,%2,%3,%4};"
                 :: "l"(o), "f"(attn * hv.x), "f"(attn * hv.y),
                    "f"(attn * hv.z), "f"(attn * hv.w)
                 : "memory");
}

__global__ void elu_kernel() {
    const int i = blockIdx.x * blockDim.x + threadIdx.x;
    if (i < NN * HC) {
        const float v = g_out[i];
        g_out[i] = v > 0.f ? v : expm1f(v);
    }
}

__global__ void logits_kernel(const float* __restrict__ Wc2,
                              const float* __restrict__ bc2,
                              float* __restrict__ out) {
    const int i = blockIdx.x * blockDim.x + threadIdx.x;
    if (i >= NN * 10) return;
    const int n = i / 10, j = i - n * 10;
    const float* z = g_z + (size_t)n * CH;
    float acc = bc2[j];
#pragma unroll 4
    for (int k = 0; k < CH; k++) acc += z[k] * Wc2[k * 10 + j];
    out[i] = acc;
}

// ---------------- launch ---------------------------------------------------
extern "C" void kernel_launch(void* const* d_in, const int* in_sizes, int n_in,
                              void* d_out, int out_size) {
    const float* x   = (const float*)d_in[0];
    const void*  ei  = d_in[1];
    const float* W1  = (const float*)d_in[2];
    const float* as1 = (const float*)d_in[3];
    const float* ad1 = (const float*)d_in[4];
    const float* b1  = (const float*)d_in[5];
    const float* W2  = (const float*)d_in[6];
    const float* as2 = (const float*)d_in[7];
    const float* ad2 = (const float*)d_in[8];
    const float* b2  = (const float*)d_in[9];
    const float* Wc1 = (const float*)d_in[10];
    const float* bc1 = (const float*)d_in[11];
    const float* Wc2 = (const float*)d_in[12];
    const float* bc2 = (const float*)d_in[13];
    float* out = (float*)d_out;

    static float* p_h = nullptr; static float* p_out = nullptr; static float* p_z = nullptr;
    static __nv_bfloat16 *p_ahi = nullptr, *p_alo = nullptr, *p_bhi = nullptr, *p_blo = nullptr;
    if (!p_h) {
        cudaGetSymbolAddress((void**)&p_h,   g_h);
        cudaGetSymbolAddress((void**)&p_out, g_out);
        cudaGetSymbolAddress((void**)&p_z,   g_z);
        cudaGetSymbolAddress((void**)&p_ahi, g_ahi);
        cudaGetSymbolAddress((void**)&p_alo, g_alo);
        cudaGetSymbolAddress((void**)&p_bhi, g_bhi);
        cudaGetSymbolAddress((void**)&p_blo, g_blo);
    }

    const int TPB = 256;
    const int alphaBlocks = (NN * NH * 32 + TPB - 1) / TPB;
    const int bigBlocks   = (NN * HC + TPB - 1) / TPB;
    const int eBlocks     = (NEP * NH + TPB - 1) / TPB;
    const int cvtBlocks   = (NEP + TPB - 1) / TPB;
    const dim3 gG512(HC / 64, MPAD / 128);
    const dim3 gG128(CH / 64, MPAD / 128);

    // ---- edge-index prep ----
    probe_kernel<<<1, 1>>>(ei);
    convert_kernel<<<cvtBlocks, TPB>>>(ei);

    // ---- layer 1 ----
    conv_w<<<(HC * KP1 + TPB - 1) / TPB, TPB>>>(W1, FIN, HC, KP1);
    conv_a<<<(MPAD * KP1 + TPB - 1) / TPB, TPB>>>(x, FIN, KP1);
    gemm_mma<0><<<gG512, TPB>>>(p_ahi, p_alo, p_bhi, p_blo, p_h, KP1, HC, nullptr);
    alpha_kernel<<<alphaBlocks, TPB>>>(as1, ad1);
    init_kernel<<<bigBlocks, TPB>>>(b1);
    edge_pass1<<<eBlocks, TPB>>>();
    edge_pass2<<<eBlocks, TPB>>>();
    edge_scatter<<<NEP, 128>>>();
    elu_kernel<<<bigBlocks, TPB>>>();

    // ---- layer 2 ----
    conv_w<<<(HC * KP2 + TPB - 1) / TPB, TPB>>>(W2, HC, HC, KP2);
    conv_a<<<(MPAD * KP2 + TPB - 1) / TPB, TPB>>>(p_out, HC, KP2);
    gemm_mma<0><<<gG512, TPB>>>(p_ahi, p_alo, p_bhi, p_blo, p_h, KP2, HC, nullptr);
    alpha_kernel<<<alphaBlocks, TPB>>>(as2, ad2);
    init_kernel<<<bigBlocks, TPB>>>(b2);
    edge_pass1<<<eBlocks, TPB>>>();
    edge_pass2<<<eBlocks, TPB>>>();
    edge_scatter<<<NEP, 128>>>();

    // ---- classifier ----
    conv_w<<<(CH * KP2 + TPB - 1) / TPB, TPB>>>(Wc1, HC, CH, KP2);
    conv_a<<<(MPAD * KP2 + TPB - 1) / TPB, TPB>>>(p_out, HC, KP2);
    gemm_mma<1><<<gG128, TPB>>>(p_ahi, p_alo, p_bhi, p_blo, p_z, KP2, CH, bc1);
    logits_kernel<<<(NN * 10 + TPB - 1) / TPB, TPB>>>(Wc2, bc2, out);
}

// round 7
// speedup vs baseline: 2.4555x; 1.8558x over previous
#include <cuda_runtime.h>
#include <cuda_bf16.h>
#include <cstdint>

#define NN   50000
#define FIN  336
#define HC   512
#define NH   4
#define CH   128
#define NE   500000
#define NEP  (NE + NN)
#define MPAD 50048            // 391 * 128
#define KP1  384              // FIN padded to 64-multiple
#define KP2  512
#define NBLK 196              // ceil(NN/256) scan blocks

// ---------------- scratch (device globals; no allocation allowed) ----------
__device__ __align__(16) float g_h[(size_t)NN * HC];
__device__ __align__(16) float g_out[(size_t)NN * HC];
__device__ __align__(16) float g_z[(size_t)NN * CH];
__device__ __align__(16) float g_asrc[NN * NH];
__device__ __align__(16) float g_adst[NN * NH];
__device__ int g_src[NEP];
__device__ int g_dst[NEP];
__device__ int g_csr[NEP];            // src indices sorted by dst
__device__ int g_deg[NN];
__device__ int g_scan[NN];
__device__ int g_bsum[256];
__device__ int g_rowptr[NN + 1];
__device__ int g_cursor[NN];
__device__ int g_is64;

// bf16 split planes for tensor-core GEMM
__device__ __align__(16) __nv_bfloat16 g_ahi[(size_t)MPAD * KP2];
__device__ __align__(16) __nv_bfloat16 g_alo[(size_t)MPAD * KP2];
__device__ __align__(16) __nv_bfloat16 g_bhi[(size_t)HC * KP2];
__device__ __align__(16) __nv_bfloat16 g_blo[(size_t)HC * KP2];

// ---------------- helpers ---------------------------------------------------
__device__ __forceinline__ uint32_t smem_u32(const void* p) {
    uint32_t a;
    asm("{ .reg .u64 t; cvta.to.shared.u64 t, %1; cvt.u32.u64 %0, t; }" : "=r"(a) : "l"(p));
    return a;
}

#define LDMX4(r0, r1, r2, r3, addr)                                            \
    asm volatile("ldmatrix.sync.aligned.m8n8.x4.shared.b16 {%0,%1,%2,%3}, [%4];" \
                 : "=r"(r0), "=r"(r1), "=r"(r2), "=r"(r3) : "r"(addr))

#define MMA16816(c, a, b0, b1)                                                 \
    asm volatile("mma.sync.aligned.m16n8k16.row.col.f32.bf16.bf16.f32 "        \
                 "{%0,%1,%2,%3}, {%4,%5,%6,%7}, {%8,%9}, {%0,%1,%2,%3};"       \
                 : "+f"((c)[0]), "+f"((c)[1]), "+f"((c)[2]), "+f"((c)[3])      \
                 : "r"((a)[0]), "r"((a)[1]), "r"((a)[2]), "r"((a)[3]),         \
                   "r"(b0), "r"(b1))

// ---------------- split-bf16 conversions ------------------------------------
// vectorized: one thread per 4 source floats
__global__ void conv_a(const float* __restrict__ src, int Kin, int Kpad) {
    const int idx = blockIdx.x * blockDim.x + threadIdx.x;
    const int qpr = Kpad >> 2;
    if (idx >= MPAD * qpr) return;
    const int row = idx / qpr, col = (idx - row * qpr) << 2;
    float4 v = make_float4(0.f, 0.f, 0.f, 0.f);
    if (row < NN && col < Kin)                      // Kin % 4 == 0
        v = *(const float4*)(src + (size_t)row * Kin + col);
    __nv_bfloat162 h01 = __floats2bfloat162_rn(v.x, v.y);
    __nv_bfloat162 h23 = __floats2bfloat162_rn(v.z, v.w);
    __nv_bfloat162 l01 = __floats2bfloat162_rn(v.x - __bfloat162float(h01.x),
                                               v.y - __bfloat162float(h01.y));
    __nv_bfloat162 l23 = __floats2bfloat162_rn(v.z - __bfloat162float(h23.x),
                                               v.w - __bfloat162float(h23.y));
    *(uint2*)(g_ahi + (size_t)idx * 4) = make_uint2(
        *(uint32_t*)&h01, *(uint32_t*)&h23);
    *(uint2*)(g_alo + (size_t)idx * 4) = make_uint2(
        *(uint32_t*)&l01, *(uint32_t*)&l23);
}

// W[K,N] row-major -> Bt[N][Kpad] K-major split planes
__global__ void conv_w(const float* __restrict__ W, int K, int N, int Kpad) {
    int idx = blockIdx.x * blockDim.x + threadIdx.x;
    if (idx >= N * Kpad) return;
    int n = idx / Kpad, k = idx - n * Kpad;
    float v = (k < K) ? W[(size_t)k * N + n] : 0.f;
    __nv_bfloat16 h = __float2bfloat16(v);
    g_bhi[idx] = h;
    g_blo[idx] = __float2bfloat16(v - __bfloat162float(h));
}

// ---------------- mma.sync GEMM: C[M,N] = A[M,K] @ Bt[N,K]^T ----------------
#define APITCH 40
template <int ACT>
__global__ void __launch_bounds__(256, 2) gemm_mma(
    const __nv_bfloat16* __restrict__ Ahi, const __nv_bfloat16* __restrict__ Alo,
    const __nv_bfloat16* __restrict__ Bhi, const __nv_bfloat16* __restrict__ Blo,
    float* __restrict__ C, int Kpad, int ldc, const float* __restrict__ bias) {
    __shared__ __align__(16) __nv_bfloat16 sAh[128 * APITCH];
    __shared__ __align__(16) __nv_bfloat16 sAl[128 * APITCH];
    __shared__ __align__(16) __nv_bfloat16 sBh[64 * APITCH];
    __shared__ __align__(16) __nv_bfloat16 sBl[64 * APITCH];

    const int tid = threadIdx.x, lane = tid & 31, wid = tid >> 5;
    const int wm = wid & 3, wn = wid >> 2;
    const int n0 = blockIdx.x * 64, m0 = blockIdx.y * 128;

    const uint32_t sAh_u = smem_u32(sAh), sAl_u = smem_u32(sAl);
    const uint32_t sBh_u = smem_u32(sBh), sBl_u = smem_u32(sBl);

    const uint32_t aoff = ((wm * 32 + (lane & 15)) * APITCH + (lane >> 4) * 8) * 2;
    const uint32_t boff = ((wn * 32 + (lane & 7) + (lane >> 4) * 8) * APITCH
                          + ((lane >> 3) & 1) * 8) * 2;

    float acc[2][4][4] = {};

    for (int k0 = 0; k0 < Kpad; k0 += 32) {
        {
            const __nv_bfloat16* aH = Ahi + (size_t)m0 * Kpad + k0;
            const __nv_bfloat16* aL = Alo + (size_t)m0 * Kpad + k0;
#pragma unroll
            for (int e = tid; e < 512; e += 256) {
                const int row = e >> 2, ch = e & 3;
                const size_t gi = (size_t)row * Kpad + ch * 8;
                const int si = row * APITCH + ch * 8;
                *(uint4*)(sAh + si) = *(const uint4*)(aH + gi);
                *(uint4*)(sAl + si) = *(const uint4*)(aL + gi);
            }
            const __nv_bfloat16* bH = Bhi + (size_t)n0 * Kpad + k0;
            const __nv_bfloat16* bL = Blo + (size_t)n0 * Kpad + k0;
            {
                const int row = tid >> 2, ch = tid & 3;
                const size_t gi = (size_t)row * Kpad + ch * 8;
                const int si = row * APITCH + ch * 8;
                *(uint4*)(sBh + si) = *(const uint4*)(bH + gi);
                *(uint4*)(sBl + si) = *(const uint4*)(bL + gi);
            }
        }
        __syncthreads();

#pragma unroll
        for (int ks = 0; ks < 2; ks++) {
            const uint32_t kb = ks * 32;
            uint32_t ah[2][4], al[2][4], bh[2][4], bl[2][4];
#pragma unroll
            for (int mi = 0; mi < 2; mi++) {
                const uint32_t ad = aoff + mi * (16 * APITCH * 2) + kb;
                LDMX4(ah[mi][0], ah[mi][1], ah[mi][2], ah[mi][3], sAh_u + ad);
                LDMX4(al[mi][0], al[mi][1], al[mi][2], al[mi][3], sAl_u + ad);
            }
#pragma unroll
            for (int g = 0; g < 2; g++) {
                const uint32_t bd = boff + g * (16 * APITCH * 2) + kb;
                LDMX4(bh[g][0], bh[g][1], bh[g][2], bh[g][3], sBh_u + bd);
                LDMX4(bl[g][0], bl[g][1], bl[g][2], bl[g][3], sBl_u + bd);
            }
#pragma unroll
            for (int mi = 0; mi < 2; mi++)
#pragma unroll
                for (int ni = 0; ni < 4; ni++) {
                    const int g = ni >> 1, p = (ni & 1) * 2;
                    MMA16816(acc[mi][ni], ah[mi], bh[g][p], bh[g][p + 1]);
                    MMA16816(acc[mi][ni], ah[mi], bl[g][p], bl[g][p + 1]);
                    MMA16816(acc[mi][ni], al[mi], bh[g][p], bh[g][p + 1]);
                }
        }
        __syncthreads();
    }

#pragma unroll
    for (int mi = 0; mi < 2; mi++) {
        const int r0 = m0 + wm * 32 + mi * 16 + (lane >> 2);
        const int r1 = r0 + 8;
#pragma unroll
        for (int ni = 0; ni < 4; ni++) {
            const int c = n0 + wn * 32 + ni * 8 + (lane & 3) * 2;
            float2 v0 = make_float2(acc[mi][ni][0], acc[mi][ni][1]);
            float2 v1 = make_float2(acc[mi][ni][2], acc[mi][ni][3]);
            if (ACT == 1) {
                const float b0 = bias[c], b1 = bias[c + 1];
                v0.x = fmaxf(v0.x + b0, 0.f); v0.y = fmaxf(v0.y + b1, 0.f);
                v1.x = fmaxf(v1.x + b0, 0.f); v1.y = fmaxf(v1.y + b1, 0.f);
            }
            if (r0 < NN) *(float2*)(C + (size_t)r0 * ldc + c) = v0;
            if (r1 < NN) *(float2*)(C + (size_t)r1 * ldc + c) = v1;
        }
    }
}

// ---------------- edge-index probe / convert / CSR build -------------------
__global__ void probe_kernel(const void* __restrict__ ei) {
    const long long* p = (const long long*)ei;
    int ok64 = 1;
    for (int i = 0; i < 64; i++) {
        long long v = p[i];
        if (v < 0 || v >= NN) ok64 = 0;
    }
    g_is64 = ok64;
}

__global__ void zero_deg() {
    const int i = blockIdx.x * blockDim.x + threadIdx.x;
    if (i < NN) g_deg[i] = 0;
}

__global__ void convert_kernel(const void* __restrict__ ei) {
    const int i = blockIdx.x * blockDim.x + threadIdx.x;
    if (i >= NEP) return;
    int s, d;
    if (i < NE) {
        if (g_is64) {
            const long long* p = (const long long*)ei;
            s = (int)p[i]; d = (int)p[NE + i];
        } else {
            const int* p = (const int*)ei;
            s = p[i]; d = p[NE + i];
        }
    } else {
        s = d = i - NE;
    }
    g_src[i] = s;
    g_dst[i] = d;
    atomicAdd(&g_deg[d], 1);
}

__global__ void scan1() {
    __shared__ int sd[256];
    const int b = blockIdx.x, t = threadIdx.x, i = b * 256 + t;
    int v = (i < NN) ? g_deg[i] : 0;
    sd[t] = v;
    __syncthreads();
#pragma unroll
    for (int o = 1; o < 256; o <<= 1) {
        int x = (t >= o) ? sd[t - o] : 0;
        __syncthreads();
        sd[t] += x;
        __syncthreads();
    }
    if (i < NN) g_scan[i] = sd[t];
    if (t == 255) g_bsum[b] = sd[255];
}

__global__ void scan2() {
    __shared__ int sd[256];
    const int t = threadIdx.x;
    sd[t] = (t < NBLK) ? g_bsum[t] : 0;
    __syncthreads();
#pragma unroll
    for (int o = 1; o < 256; o <<= 1) {
        int x = (t >= o) ? sd[t - o] : 0;
        __syncthreads();
        sd[t] += x;
        __syncthreads();
    }
    if (t < NBLK) g_bsum[t] = sd[t];
}

__global__ void scan3() {
    const int i = blockIdx.x * blockDim.x + threadIdx.x;
    if (i >= NN) return;
    const int b = i >> 8;
    const int incl = g_scan[i] + (b > 0 ? g_bsum[b - 1] : 0);
    g_rowptr[i + 1] = incl;
    g_cursor[i] = incl - g_deg[i];
    if (i == 0) g_rowptr[0] = 0;
}

__global__ void csr_scatter() {
    const int e = blockIdx.x * blockDim.x + threadIdx.x;
    if (e >= NEP) return;
    const int pos = atomicAdd(&g_cursor[g_dst[e]], 1);
    g_csr[pos] = g_src[e];
}

// ---------------- alpha coefficients ----------------------------------------
__global__ void alpha_kernel(const float* __restrict__ asrc,
                             const float* __restrict__ adst) {
    const int w = (blockIdx.x * blockDim.x + threadIdx.x) >> 5;
    const int lane = threadIdx.x & 31;
    if (w >= NN * NH) return;
    const int n = w >> 2, hd = w & 3;
    const float4 hv = *(const float4*)(g_h + (size_t)n * HC + hd * CH + lane * 4);
    const float4 as = *(const float4*)(asrc + hd * CH + lane * 4);
    const float4 ad = *(const float4*)(adst + hd * CH + lane * 4);
    float ss = hv.x * as.x + hv.y * as.y + hv.z * as.z + hv.w * as.w;
    float sd = hv.x * ad.x + hv.y * ad.y + hv.z * ad.z + hv.w * ad.w;
#pragma unroll
    for (int o = 16; o > 0; o >>= 1) {
        ss += __shfl_xor_sync(0xffffffffu, ss, o);
        sd += __shfl_xor_sync(0xffffffffu, sd, o);
    }
    if (lane == 0) { g_asrc[w] = ss; g_adst[w] = sd; }
}

// ---------------- fused gather aggregation (online softmax) ----------------
// one 128-thread block per dst node; thread t owns channels [4t, 4t+4)
template <int DO_ELU>
__global__ void __launch_bounds__(128) agg_kernel(const float* __restrict__ bias) {
    __shared__ __align__(16) float4 se[128];
    __shared__ int ssrc[128];
    __shared__ float scm[NH];

    const int d = blockIdx.x, t = threadIdx.x, hd = t >> 5;
    const int beg = g_rowptr[d], end = g_rowptr[d + 1];
    const float4 ad = *(const float4*)(g_adst + d * NH);

    float4 acc = make_float4(0.f, 0.f, 0.f, 0.f);
    float m = __int_as_float(0xff800000);   // -inf
    float s = 0.f;

    for (int c0 = beg; c0 < end; c0 += 128) {
        const int cnt = min(128, end - c0);
        __syncthreads();
        if (t < cnt) {
            const int sidx = g_csr[c0 + t];
            ssrc[t] = sidx;
            float4 a = *(const float4*)(g_asrc + sidx * NH);
            a.x += ad.x; a.y += ad.y; a.z += ad.z; a.w += ad.w;
            a.x = a.x > 0.f ? a.x : 0.2f * a.x;
            a.y = a.y > 0.f ? a.y : 0.2f * a.y;
            a.z = a.z > 0.f ? a.z : 0.2f * a.z;
            a.w = a.w > 0.f ? a.w : 0.2f * a.w;
            se[t] = a;
        }
        __syncthreads();

        // chunk max for this thread's head (identical across the 32 lanes)
        float cm = m;
        for (int j = 0; j < cnt; j++) cm = fmaxf(cm, ((const float*)&se[j])[hd]);
        const float scale = expf(m - cm);   // 0 when m == -inf
        acc.x *= scale; acc.y *= scale; acc.z *= scale; acc.w *= scale;
        s *= scale;
        m = cm;
        if ((t & 31) == 0) scm[hd] = cm;
        __syncthreads();

        // p = exp(e - m), computed once per (edge, head), in place
        for (int idx = t; idx < cnt * NH; idx += 128) {
            const int j = idx >> 2, h = idx & 3;
            ((float*)&se[j])[h] = expf(((const float*)&se[j])[h] - scm[h]);
        }
        __syncthreads();

        for (int j = 0; j < cnt; j++) {
            const float p = ((const float*)&se[j])[hd];
            s += p;
            const float4 hv = *(const float4*)(g_h + (size_t)ssrc[j] * HC + t * 4);
            acc.x += p * hv.x; acc.y += p * hv.y;
            acc.z += p * hv.z; acc.w += p * hv.w;
        }
    }

    const float inv = 1.f / (s + 1e-16f);
    const int c = t * 4;
    const float4 b4 = *(const float4*)(bias + c);
    float4 o = make_float4(acc.x * inv + b4.x, acc.y * inv + b4.y,
                           acc.z * inv + b4.z, acc.w * inv + b4.w);
    if (DO_ELU) {
        o.x = o.x > 0.f ? o.x : expm1f(o.x);
        o.y = o.y > 0.f ? o.y : expm1f(o.y);
        o.z = o.z > 0.f ? o.z : expm1f(o.z);
        o.w = o.w > 0.f ? o.w : expm1f(o.w);
    }
    *(float4*)(g_out + (size_t)d * HC + c) = o;
}

// ---------------- classifier tail -------------------------------------------
__global__ void logits_kernel(const float* __restrict__ Wc2,
                              const float* __restrict__ bc2,
                              float* __restrict__ out) {
    const int i = blockIdx.x * blockDim.x + threadIdx.x;
    if (i >= NN * 10) return;
    const int n = i / 10, j = i - n * 10;
    const float* z = g_z + (size_t)n * CH;
    float acc = bc2[j];
#pragma unroll 4
    for (int k = 0; k < CH; k++) acc += z[k] * Wc2[k * 10 + j];
    out[i] = acc;
}

// ---------------- launch ---------------------------------------------------
extern "C" void kernel_launch(void* const* d_in, const int* in_sizes, int n_in,
                              void* d_out, int out_size) {
    const float* x   = (const float*)d_in[0];
    const void*  ei  = d_in[1];
    const float* W1  = (const float*)d_in[2];
    const float* as1 = (const float*)d_in[3];
    const float* ad1 = (const float*)d_in[4];
    const float* b1  = (const float*)d_in[5];
    const float* W2  = (const float*)d_in[6];
    const float* as2 = (const float*)d_in[7];
    const float* ad2 = (const float*)d_in[8];
    const float* b2  = (const float*)d_in[9];
    const float* Wc1 = (const float*)d_in[10];
    const float* bc1 = (const float*)d_in[11];
    const float* Wc2 = (const float*)d_in[12];
    const float* bc2 = (const float*)d_in[13];
    float* out = (float*)d_out;

    static float* p_h = nullptr; static float* p_out = nullptr; static float* p_z = nullptr;
    static __nv_bfloat16 *p_ahi = nullptr, *p_alo = nullptr, *p_bhi = nullptr, *p_blo = nullptr;
    if (!p_h) {
        cudaGetSymbolAddress((void**)&p_h,   g_h);
        cudaGetSymbolAddress((void**)&p_out, g_out);
        cudaGetSymbolAddress((void**)&p_z,   g_z);
        cudaGetSymbolAddress((void**)&p_ahi, g_ahi);
        cudaGetSymbolAddress((void**)&p_alo, g_alo);
        cudaGetSymbolAddress((void**)&p_bhi, g_bhi);
        cudaGetSymbolAddress((void**)&p_blo, g_blo);
    }

    const int TPB = 256;
    const int alphaBlocks = (NN * NH * 32 + TPB - 1) / TPB;
    const int eBlocks     = (NEP + TPB - 1) / TPB;
    const int nodeBlocks  = (NN + TPB - 1) / TPB;
    const dim3 gG512(HC / 64, MPAD / 128);
    const dim3 gG128(CH / 64, MPAD / 128);

    // ---- CSR build ----
    probe_kernel<<<1, 1>>>(ei);
    zero_deg<<<nodeBlocks, TPB>>>();
    convert_kernel<<<eBlocks, TPB>>>(ei);
    scan1<<<NBLK, 256>>>();
    scan2<<<1, 256>>>();
    scan3<<<nodeBlocks, TPB>>>();
    csr_scatter<<<eBlocks, TPB>>>();

    // ---- layer 1 ----
    conv_w<<<(HC * KP1 + TPB - 1) / TPB, TPB>>>(W1, FIN, HC, KP1);
    conv_a<<<(MPAD * KP1 / 4 + TPB - 1) / TPB, TPB>>>(x, FIN, KP1);
    gemm_mma<0><<<gG512, TPB>>>(p_ahi, p_alo, p_bhi, p_blo, p_h, KP1, HC, nullptr);
    alpha_kernel<<<alphaBlocks, TPB>>>(as1, ad1);
    agg_kernel<1><<<NN, 128>>>(b1);

    // ---- layer 2 ----
    conv_w<<<(HC * KP2 + TPB - 1) / TPB, TPB>>>(W2, HC, HC, KP2);
    conv_a<<<(MPAD * KP2 / 4 + TPB - 1) / TPB, TPB>>>(p_out, HC, KP2);
    gemm_mma<0><<<gG512, TPB>>>(p_ahi, p_alo, p_bhi, p_blo, p_h, KP2, HC, nullptr);
    alpha_kernel<<<alphaBlocks, TPB>>>(as2, ad2);
    agg_kernel<0><<<NN, 128>>>(b2);

    // ---- classifier ----
    conv_w<<<(CH * KP2 + TPB - 1) / TPB, TPB>>>(Wc1, HC, CH, KP2);
    conv_a<<<(MPAD * KP2 / 4 + TPB - 1) / TPB, TPB>>>(p_out, HC, KP2);
    gemm_mma<1><<<gG128, TPB>>>(p_ahi, p_alo, p_bhi, p_blo, p_z, KP2, CH, bc1);
    logits_kernel<<<(NN * 10 + TPB - 1) / TPB, TPB>>>(Wc2, bc2, out);
}